// round 4
// baseline (speedup 1.0000x reference)
#include <cuda_runtime.h>

typedef unsigned long long ull;

#define Hs      49
#define HP      64           // padded units
#define G4      196
#define NL      7
#define IN0     7
#define NOUT    7
#define BATCH   1024
#define TT      512

// ---------------- device scratch (no runtime allocation allowed) ----------
__device__ float g_wrec[NL][Hs][HP][4];       // recurrent W: [l][k][u][gate i,f,g,o]
__device__ float g_wx[NL][Hs][HP][4][2];      // input W, gate-duplicated pairs
__device__ float g_bias[NL][HP][4][2];        // (b_ih+b_hh), duplicated
__device__ float g_pre[TT][Hs][BATCH][4];     // input projections [t][u][b][gate]
__device__ float g_h[TT][BATCH][Hs];          // layer output [t][b][u]

// ---------------- f32x2 helpers -------------------------------------------
static __device__ __forceinline__ void unpack2(ull v, float &lo, float &hi) {
    asm("mov.b64 {%0,%1}, %2;" : "=f"(lo), "=f"(hi) : "l"(v));
}
static __device__ __forceinline__ ull ffma2(ull a, ull b, ull c) {
    ull d;
    asm("fma.rn.f32x2 %0, %1, %2, %3;" : "=l"(d) : "l"(a), "l"(b), "l"(c));
    return d;
}
static __device__ __forceinline__ float sigf(float x)   { return 1.f / (1.f + __expf(-x)); }
static __device__ __forceinline__ float tanhf2(float x) { return 1.f - 2.f / (1.f + __expf(2.f * x)); }

// ---------------- weight / bias packing -----------------------------------
__global__ void pack_kernel(const float* __restrict__ W_ih0,
                            const float* __restrict__ W_ihr,
                            const float* __restrict__ W_hh,
                            const float* __restrict__ b_ih,
                            const float* __restrict__ b_hh) {
    int idx = blockIdx.x * blockDim.x + threadIdx.x;
    const int total = NL * Hs * HP * 4;
    if (idx >= total) return;
    int l   = idx / (Hs * HP * 4);
    int rem = idx % (Hs * HP * 4);
    int k   = rem / (HP * 4);
    int ug  = rem % (HP * 4);
    int u = ug >> 2, j = ug & 3;
    int row = j * Hs + u;                        // torch gate order i,f,g,o

    float wr = 0.f, wx = 0.f;
    if (u < Hs) {
        wr = W_hh[(l * G4 + row) * Hs + k];
        if (l == 0) {
            if (k < IN0) wx = W_ih0[row * IN0 + k];
        } else {
            wx = W_ihr[((l - 1) * G4 + row) * Hs + k];
        }
    }
    g_wrec[l][k][u][j]  = wr;
    g_wx[l][k][u][j][0] = wx;
    g_wx[l][k][u][j][1] = wx;
    if (k == 0) {
        float bs = (u < Hs) ? (b_ih[l * G4 + row] + b_hh[l * G4 + row]) : 0.f;
        g_bias[l][u][j][0] = bs;
        g_bias[l][u][j][1] = bs;
    }
}

// ---------------- input-projection GEMM ------------------------------------
// pre[t][u][b][j] = bias[u][j] + sum_k in[t][b][k] * Wx[k][u][j]
#define PG_TPB  256
#define PG_BT   32        // batch per block
#define PG_TS   4         // timesteps per block
#define IT_PAD  36        // intile row stride (floats), 144B = 16B-aligned

template<int KD>
__global__ __launch_bounds__(PG_TPB, 2)
void pre_gemm(const float* __restrict__ xin, int layer) {
    extern __shared__ float sm[];
    float* wd = sm;                          // [KD][HP][4][2]
    float* bi = wd + KD * HP * 8;            // [HP][4][2]
    float* it = bi + HP * 8;                 // [KD][IT_PAD]

    const int tid = threadIdx.x;
    const float* wsrc = &g_wx[layer][0][0][0][0];
    for (int i = tid; i < KD * HP * 8; i += PG_TPB) wd[i] = wsrc[i];
    const float* bsrc = &g_bias[layer][0][0][0];
    for (int i = tid; i < HP * 8; i += PG_TPB) bi[i] = bsrc[i];

    const int warp = tid >> 5, lane = tid & 31;
    const int u  = (warp << 3) | (lane >> 2);
    const int bq = lane & 3;
    const int bbase = blockIdx.x * PG_BT;
    const int t0    = blockIdx.y * PG_TS;

    __syncthreads();

    // bias into regs (duplicated pairs)
    ull bj[4];
    {
        const ulonglong2* bp2 = (const ulonglong2*)(bi + u * 8);
        ulonglong2 A = bp2[0], B = bp2[1];
        bj[0] = A.x; bj[1] = A.y; bj[2] = B.x; bj[3] = B.y;
    }

    for (int ti = 0; ti < PG_TS; ti++) {
        const int t = t0 + ti;
        __syncthreads();
        // stage input tile transposed: it[k][bb] = in[t][bbase+bb][k]
        if (layer == 0) {
            for (int i = tid; i < KD * PG_BT; i += PG_TPB) {
                int k = i / PG_BT, bb = i % PG_BT;
                it[k * IT_PAD + bb] = xin[((long long)(bbase + bb) * TT + t) * IN0 + k];
            }
        } else {
            for (int i = tid; i < KD * PG_BT; i += PG_TPB) {
                int bb = i / KD, k = i % KD;
                it[k * IT_PAD + bb] = g_h[t][bbase + bb][k];
            }
        }
        __syncthreads();

        ull acc[4][4];
#pragma unroll
        for (int j = 0; j < 4; j++)
#pragma unroll
            for (int p = 0; p < 4; p++) acc[j][p] = bj[j];

#pragma unroll 7
        for (int k = 0; k < KD; k++) {
            const ulonglong2* wr = (const ulonglong2*)(wd + k * HP * 8 + u * 8);
            ulonglong2 W0 = wr[0], W1 = wr[1];       // (wi,wi)(wf,wf)(wg,wg)(wo,wo)
            const ulonglong2* xr = (const ulonglong2*)(it + k * IT_PAD + bq * 8);
            ulonglong2 X0 = xr[0], X1 = xr[1];       // 4 batch-pairs
            acc[0][0] = ffma2(W0.x, X0.x, acc[0][0]);
            acc[0][1] = ffma2(W0.x, X0.y, acc[0][1]);
            acc[0][2] = ffma2(W0.x, X1.x, acc[0][2]);
            acc[0][3] = ffma2(W0.x, X1.y, acc[0][3]);
            acc[1][0] = ffma2(W0.y, X0.x, acc[1][0]);
            acc[1][1] = ffma2(W0.y, X0.y, acc[1][1]);
            acc[1][2] = ffma2(W0.y, X1.x, acc[1][2]);
            acc[1][3] = ffma2(W0.y, X1.y, acc[1][3]);
            acc[2][0] = ffma2(W1.x, X0.x, acc[2][0]);
            acc[2][1] = ffma2(W1.x, X0.y, acc[2][1]);
            acc[2][2] = ffma2(W1.x, X1.x, acc[2][2]);
            acc[2][3] = ffma2(W1.x, X1.y, acc[2][3]);
            acc[3][0] = ffma2(W1.y, X0.x, acc[3][0]);
            acc[3][1] = ffma2(W1.y, X0.y, acc[3][1]);
            acc[3][2] = ffma2(W1.y, X1.x, acc[3][2]);
            acc[3][3] = ffma2(W1.y, X1.y, acc[3][3]);
        }

        if (u < Hs) {
            float4* op = (float4*)&g_pre[t][u][bbase + bq * 8][0];
#pragma unroll
            for (int p = 0; p < 4; p++) {
                float a0, c0, a1, c1, a2, c2, a3, c3;
                unpack2(acc[0][p], a0, c0);
                unpack2(acc[1][p], a1, c1);
                unpack2(acc[2][p], a2, c2);
                unpack2(acc[3][p], a3, c3);
                op[2 * p]     = make_float4(a0, a1, a2, a3);
                op[2 * p + 1] = make_float4(c0, c1, c2, c3);
            }
        }
    }
}

// ---------------- recurrent kernel -----------------------------------------
// 128 blocks x 224 threads (7 warps). Warp = 8 units x 4 batch-pairs.
// Inner loop per k: 1 LDS.128 (w gate-pairs) + 1 LDS.128 (h duplicated) + 4 FFMA2.
#define R_TPB   224
#define R_SMEM  ((Hs*HP*4 + 2*Hs*16) * 4)

__global__ __launch_bounds__(R_TPB, 1)
void lstm_rec(int layer) {
    extern __shared__ float sm[];
    float* ws = sm;                    // [49][HP][4]
    float* vv = ws + Hs * HP * 4;      // [2][49][8][2]  (h duplicated pairs)

    const int tid = threadIdx.x;
    const float* wsrc = &g_wrec[layer][0][0][0];
    for (int i = tid; i < Hs * HP * 4; i += R_TPB) ws[i] = wsrc[i];
    for (int i = tid; i < 2 * Hs * 16; i += R_TPB) vv[i] = 0.f;

    const int warp = tid >> 5, lane = tid & 31;
    const int u  = (warp << 3) | (lane >> 2);
    const int bp = lane & 3;
    const int b0 = blockIdx.x * 8 + bp * 2;
    const bool act = (u < Hs);

    __syncthreads();

    const ulonglong2* wp = (const ulonglong2*)ws;           // index k*64 + u
    // per-t stride of g_pre in ulonglong2 (16B) units:
    // Hs*BATCH*4 floats * 4B / 16B = Hs*BATCH   (R2 bug: had an extra *2)
    const long long pstride2 = (long long)Hs * BATCH;

    ull pf0 = 0, pf1 = 0, pf2 = 0, pf3 = 0;
    const ulonglong2* pp0 = (const ulonglong2*)&g_pre[0][act ? u : 0][b0][0];
    if (act) {
        ulonglong2 A = pp0[0], B = pp0[1];
        pf0 = A.x; pf1 = A.y; pf2 = B.x; pf3 = B.y;
    }

    float c0 = 0.f, c1 = 0.f;

    for (int t = 0; t < TT; t++) {
        const int cur = t & 1, nxt = cur ^ 1;

        ull acc0 = pf0, acc1 = pf1, acc2 = pf2, acc3 = pf3;

        // prefetch pre(t+1)
        if (act && t + 1 < TT) {
            const ulonglong2* pp = pp0 + (long long)(t + 1) * pstride2;
            ulonglong2 A = pp[0], B = pp[1];
            pf0 = A.x; pf1 = A.y; pf2 = B.x; pf3 = B.y;
        }

        if (act) {
            const ulonglong2* hp = (const ulonglong2*)(vv + cur * Hs * 16);
#pragma unroll 7
            for (int k = 0; k < Hs; k++) {
                ulonglong2 W = wp[k * 64 + u];      // (wi,wf),(wg,wo)
                ulonglong2 H = hp[k * 4 + bp];      // (h0,h0),(h1,h1)
                acc0 = ffma2(W.x, H.x, acc0);
                acc1 = ffma2(W.y, H.x, acc1);
                acc2 = ffma2(W.x, H.y, acc2);
                acc3 = ffma2(W.y, H.y, acc3);
            }

            float i0, f0, g0, o0, i1, f1, g1, o1;
            unpack2(acc0, i0, f0);
            unpack2(acc1, g0, o0);
            unpack2(acc2, i1, f1);
            unpack2(acc3, g1, o1);
            i0 = sigf(i0); f0 = sigf(f0); g0 = tanhf2(g0); o0 = sigf(o0);
            i1 = sigf(i1); f1 = sigf(f1); g1 = tanhf2(g1); o1 = sigf(o1);
            c0 = f0 * c0 + i0 * g0;
            c1 = f1 * c1 + i1 * g1;
            float h0v = o0 * tanhf2(c0);
            float h1v = o1 * tanhf2(c1);

            // duplicated h pairs for next step's LDS.128
            *((float4*)(vv + (nxt * Hs + u) * 16) + bp) = make_float4(h0v, h0v, h1v, h1v);
            // layer output for next layer's pre-GEMM / FC
            g_h[t][b0][u]     = h0v;
            g_h[t][b0 + 1][u] = h1v;
        }
        __syncthreads();
    }
}

// ---------------- final FC --------------------------------------------------
#define FCB 128
__global__ void fc_kernel(const float* __restrict__ fc_w,
                          const float* __restrict__ fc_b,
                          float* __restrict__ outp) {
    __shared__ float sh[FCB * Hs];
    __shared__ float sw[NOUT * Hs + NOUT];
    int t   = blockIdx.x;
    int bc  = blockIdx.y;
    int tid = threadIdx.x;

    const float* hbuf = &g_h[0][0][0];
    for (int i = tid; i < FCB * Hs; i += FCB)
        sh[i] = hbuf[(long long)t * BATCH * Hs + (long long)bc * FCB * Hs + i];
    for (int i = tid; i < NOUT * Hs; i += FCB) sw[i] = fc_w[i];
    if (tid < NOUT) sw[NOUT * Hs + tid] = fc_b[tid];
    __syncthreads();

    int b = bc * FCB + tid;
    float o[NOUT];
#pragma unroll
    for (int j = 0; j < NOUT; j++) o[j] = sw[NOUT * Hs + j];
#pragma unroll
    for (int k = 0; k < Hs; k++) {
        float h = sh[tid * Hs + k];
#pragma unroll
        for (int j = 0; j < NOUT; j++) o[j] += h * sw[j * Hs + k];
    }
#pragma unroll
    for (int j = 0; j < NOUT; j++)
        outp[(long long)b * TT * NOUT + t * NOUT + j] = o[j];
}

// ---------------- launcher --------------------------------------------------
extern "C" void kernel_launch(void* const* d_in, const int* in_sizes, int n_in,
                              void* d_out, int out_size) {
    const float* x     = (const float*)d_in[0];
    const float* W_ih0 = (const float*)d_in[1];
    const float* W_ihr = (const float*)d_in[2];
    const float* W_hh  = (const float*)d_in[3];
    const float* b_ih  = (const float*)d_in[4];
    const float* b_hh  = (const float*)d_in[5];
    const float* fc_w  = (const float*)d_in[6];
    const float* fc_b  = (const float*)d_in[7];
    float* outp = (float*)d_out;

    const int pg_smem49 = (49 * HP * 8 + HP * 8 + 49 * IT_PAD) * 4;
    const int pg_smem7  = (7  * HP * 8 + HP * 8 + 7  * IT_PAD) * 4;
    cudaFuncSetAttribute(pre_gemm<49>, cudaFuncAttributeMaxDynamicSharedMemorySize, pg_smem49);
    cudaFuncSetAttribute(pre_gemm<7>,  cudaFuncAttributeMaxDynamicSharedMemorySize, pg_smem7);
    cudaFuncSetAttribute(lstm_rec,     cudaFuncAttributeMaxDynamicSharedMemorySize, R_SMEM);

    const int total = NL * Hs * HP * 4;
    pack_kernel<<<(total + 255) / 256, 256>>>(W_ih0, W_ihr, W_hh, b_ih, b_hh);

    dim3 pgrid(BATCH / PG_BT, TT / PG_TS);
    for (int l = 0; l < NL; l++) {
        if (l == 0) pre_gemm<7><<<pgrid, PG_TPB, pg_smem7>>>(x, l);
        else        pre_gemm<49><<<pgrid, PG_TPB, pg_smem49>>>(x, l);
        lstm_rec<<<BATCH / 8, R_TPB, R_SMEM>>>(l);
    }

    dim3 fcg(TT, BATCH / FCB);
    fc_kernel<<<fcg, FCB>>>(fc_w, fc_b, outp);
}

// round 5
// speedup vs baseline: 1.5297x; 1.5297x over previous
#include <cuda_runtime.h>

typedef unsigned long long ull;

#define Hs      49
#define HP      64           // padded units
#define G4      196
#define NL      7
#define IN0     7
#define NOUT    7
#define BATCH   1024
#define TT      512

// ---------------- device scratch (no runtime allocation allowed) ----------
__device__ float g_wrec[NL][Hs][HP][4];       // recurrent W: [l][k][u][gate i,f,g,o]
__device__ float g_wx[NL][Hs][HP][4][2];      // input W, gate-duplicated pairs
__device__ float g_bias[NL][HP][4][2];        // (b_ih+b_hh), duplicated
__device__ float g_pre[TT][Hs][BATCH][4];     // input projections [t][u][b][gate]
__device__ float g_h[TT][BATCH][Hs];          // layer output [t][b][u]

// ---------------- f32x2 helpers -------------------------------------------
static __device__ __forceinline__ void unpack2(ull v, float &lo, float &hi) {
    asm("mov.b64 {%0,%1}, %2;" : "=f"(lo), "=f"(hi) : "l"(v));
}
static __device__ __forceinline__ ull ffma2(ull a, ull b, ull c) {
    ull d;
    asm("fma.rn.f32x2 %0, %1, %2, %3;" : "=l"(d) : "l"(a), "l"(b), "l"(c));
    return d;
}
static __device__ __forceinline__ float sigf(float x)   { return 1.f / (1.f + __expf(-x)); }
static __device__ __forceinline__ float tanhf2(float x) { return 1.f - 2.f / (1.f + __expf(2.f * x)); }

// ---------------- weight / bias packing -----------------------------------
__global__ void pack_kernel(const float* __restrict__ W_ih0,
                            const float* __restrict__ W_ihr,
                            const float* __restrict__ W_hh,
                            const float* __restrict__ b_ih,
                            const float* __restrict__ b_hh) {
    int idx = blockIdx.x * blockDim.x + threadIdx.x;
    const int total = NL * Hs * HP * 4;
    if (idx >= total) return;
    int l   = idx / (Hs * HP * 4);
    int rem = idx % (Hs * HP * 4);
    int k   = rem / (HP * 4);
    int ug  = rem % (HP * 4);
    int u = ug >> 2, j = ug & 3;
    int row = j * Hs + u;                        // torch gate order i,f,g,o

    float wr = 0.f, wx = 0.f;
    if (u < Hs) {
        wr = W_hh[(l * G4 + row) * Hs + k];
        if (l == 0) {
            if (k < IN0) wx = W_ih0[row * IN0 + k];
        } else {
            wx = W_ihr[((l - 1) * G4 + row) * Hs + k];
        }
    }
    g_wrec[l][k][u][j]  = wr;
    g_wx[l][k][u][j][0] = wx;
    g_wx[l][k][u][j][1] = wx;
    if (k == 0) {
        float bs = (u < Hs) ? (b_ih[l * G4 + row] + b_hh[l * G4 + row]) : 0.f;
        g_bias[l][u][j][0] = bs;
        g_bias[l][u][j][1] = bs;
    }
}

// ---------------- input-projection GEMM ------------------------------------
// pre[t][u][b][j] = bias[u][j] + sum_k in[t][b][k] * Wx[k][u][j]
#define PG_TPB  256
#define PG_BT   32        // batch per block
#define PG_TS   4         // timesteps per block
#define IT_PAD  36        // intile row stride (floats), 144B = 16B-aligned

template<int KD>
__global__ __launch_bounds__(PG_TPB, 2)
void pre_gemm(const float* __restrict__ xin, int layer) {
    extern __shared__ float sm[];
    float* wd = sm;                          // [KD][HP][4][2]
    float* bi = wd + KD * HP * 8;            // [HP][4][2]
    float* it = bi + HP * 8;                 // [KD][IT_PAD]

    const int tid = threadIdx.x;
    const float* wsrc = &g_wx[layer][0][0][0][0];
    for (int i = tid; i < KD * HP * 8; i += PG_TPB) wd[i] = wsrc[i];
    const float* bsrc = &g_bias[layer][0][0][0];
    for (int i = tid; i < HP * 8; i += PG_TPB) bi[i] = bsrc[i];

    const int warp = tid >> 5, lane = tid & 31;
    const int u  = (warp << 3) | (lane >> 2);
    const int bq = lane & 3;
    const int bbase = blockIdx.x * PG_BT;
    const int t0    = blockIdx.y * PG_TS;

    __syncthreads();

    // bias into regs (duplicated pairs)
    ull bj[4];
    {
        const ulonglong2* bp2 = (const ulonglong2*)(bi + u * 8);
        ulonglong2 A = bp2[0], B = bp2[1];
        bj[0] = A.x; bj[1] = A.y; bj[2] = B.x; bj[3] = B.y;
    }

    for (int ti = 0; ti < PG_TS; ti++) {
        const int t = t0 + ti;
        __syncthreads();
        // stage input tile transposed: it[k][bb] = in[t][bbase+bb][k]
        if (layer == 0) {
            for (int i = tid; i < KD * PG_BT; i += PG_TPB) {
                int k = i / PG_BT, bb = i % PG_BT;
                it[k * IT_PAD + bb] = xin[((long long)(bbase + bb) * TT + t) * IN0 + k];
            }
        } else {
            for (int i = tid; i < KD * PG_BT; i += PG_TPB) {
                int bb = i / KD, k = i % KD;
                it[k * IT_PAD + bb] = g_h[t][bbase + bb][k];
            }
        }
        __syncthreads();

        ull acc[4][4];
#pragma unroll
        for (int j = 0; j < 4; j++)
#pragma unroll
            for (int p = 0; p < 4; p++) acc[j][p] = bj[j];

#pragma unroll 7
        for (int k = 0; k < KD; k++) {
            const ulonglong2* wr = (const ulonglong2*)(wd + k * HP * 8 + u * 8);
            ulonglong2 W0 = wr[0], W1 = wr[1];       // (wi,wi)(wf,wf)(wg,wg)(wo,wo)
            const ulonglong2* xr = (const ulonglong2*)(it + k * IT_PAD + bq * 8);
            ulonglong2 X0 = xr[0], X1 = xr[1];       // 4 batch-pairs
            acc[0][0] = ffma2(W0.x, X0.x, acc[0][0]);
            acc[0][1] = ffma2(W0.x, X0.y, acc[0][1]);
            acc[0][2] = ffma2(W0.x, X1.x, acc[0][2]);
            acc[0][3] = ffma2(W0.x, X1.y, acc[0][3]);
            acc[1][0] = ffma2(W0.y, X0.x, acc[1][0]);
            acc[1][1] = ffma2(W0.y, X0.y, acc[1][1]);
            acc[1][2] = ffma2(W0.y, X1.x, acc[1][2]);
            acc[1][3] = ffma2(W0.y, X1.y, acc[1][3]);
            acc[2][0] = ffma2(W1.x, X0.x, acc[2][0]);
            acc[2][1] = ffma2(W1.x, X0.y, acc[2][1]);
            acc[2][2] = ffma2(W1.x, X1.x, acc[2][2]);
            acc[2][3] = ffma2(W1.x, X1.y, acc[2][3]);
            acc[3][0] = ffma2(W1.y, X0.x, acc[3][0]);
            acc[3][1] = ffma2(W1.y, X0.y, acc[3][1]);
            acc[3][2] = ffma2(W1.y, X1.x, acc[3][2]);
            acc[3][3] = ffma2(W1.y, X1.y, acc[3][3]);
        }

        if (u < Hs) {
            float4* op = (float4*)&g_pre[t][u][bbase + bq * 8][0];
#pragma unroll
            for (int p = 0; p < 4; p++) {
                float a0, c0, a1, c1, a2, c2, a3, c3;
                unpack2(acc[0][p], a0, c0);
                unpack2(acc[1][p], a1, c1);
                unpack2(acc[2][p], a2, c2);
                unpack2(acc[3][p], a3, c3);
                op[2 * p]     = make_float4(a0, a1, a2, a3);
                op[2 * p + 1] = make_float4(c0, c1, c2, c3);
            }
        }
    }
}

// ---------------- recurrent kernel -----------------------------------------
// 128 blocks x 224 threads (7 warps). Warp = 8 units x 4 batch-pairs.
// Inner loop per k: 1 LDS.128 (w gate-pairs) + 1 LDS.128 (h duplicated) + 4 FFMA2.
#define R_TPB   224
#define R_SMEM  ((Hs*HP*4 + 2*Hs*16) * 4)

__global__ __launch_bounds__(R_TPB, 1)
void lstm_rec(int layer) {
    extern __shared__ float sm[];
    float* ws = sm;                    // [49][HP][4]
    float* vv = ws + Hs * HP * 4;      // [2][49][8][2]  (h duplicated pairs)

    const int tid = threadIdx.x;
    const float* wsrc = &g_wrec[layer][0][0][0];
    for (int i = tid; i < Hs * HP * 4; i += R_TPB) ws[i] = wsrc[i];
    for (int i = tid; i < 2 * Hs * 16; i += R_TPB) vv[i] = 0.f;

    const int warp = tid >> 5, lane = tid & 31;
    const int u  = (warp << 3) | (lane >> 2);
    const int bp = lane & 3;
    const int b0 = blockIdx.x * 8 + bp * 2;
    const bool act = (u < Hs);

    __syncthreads();

    const ulonglong2* wp = (const ulonglong2*)ws;           // index k*64 + u
    // per-t stride of g_pre in ulonglong2 (16B) units:
    // Hs*BATCH*4 floats * 4B / 16B = Hs*BATCH   (R2 bug: had an extra *2)
    const long long pstride2 = (long long)Hs * BATCH;

    ull pf0 = 0, pf1 = 0, pf2 = 0, pf3 = 0;
    const ulonglong2* pp0 = (const ulonglong2*)&g_pre[0][act ? u : 0][b0][0];
    if (act) {
        ulonglong2 A = pp0[0], B = pp0[1];
        pf0 = A.x; pf1 = A.y; pf2 = B.x; pf3 = B.y;
    }

    float c0 = 0.f, c1 = 0.f;

    for (int t = 0; t < TT; t++) {
        const int cur = t & 1, nxt = cur ^ 1;

        ull acc0 = pf0, acc1 = pf1, acc2 = pf2, acc3 = pf3;

        // prefetch pre(t+1)
        if (act && t + 1 < TT) {
            const ulonglong2* pp = pp0 + (long long)(t + 1) * pstride2;
            ulonglong2 A = pp[0], B = pp[1];
            pf0 = A.x; pf1 = A.y; pf2 = B.x; pf3 = B.y;
        }

        if (act) {
            const ulonglong2* hp = (const ulonglong2*)(vv + cur * Hs * 16);
#pragma unroll 7
            for (int k = 0; k < Hs; k++) {
                ulonglong2 W = wp[k * 64 + u];      // (wi,wf),(wg,wo)
                ulonglong2 H = hp[k * 4 + bp];      // (h0,h0),(h1,h1)
                acc0 = ffma2(W.x, H.x, acc0);
                acc1 = ffma2(W.y, H.x, acc1);
                acc2 = ffma2(W.x, H.y, acc2);
                acc3 = ffma2(W.y, H.y, acc3);
            }

            float i0, f0, g0, o0, i1, f1, g1, o1;
            unpack2(acc0, i0, f0);
            unpack2(acc1, g0, o0);
            unpack2(acc2, i1, f1);
            unpack2(acc3, g1, o1);
            i0 = sigf(i0); f0 = sigf(f0); g0 = tanhf2(g0); o0 = sigf(o0);
            i1 = sigf(i1); f1 = sigf(f1); g1 = tanhf2(g1); o1 = sigf(o1);
            c0 = f0 * c0 + i0 * g0;
            c1 = f1 * c1 + i1 * g1;
            float h0v = o0 * tanhf2(c0);
            float h1v = o1 * tanhf2(c1);

            // duplicated h pairs for next step's LDS.128
            *((float4*)(vv + (nxt * Hs + u) * 16) + bp) = make_float4(h0v, h0v, h1v, h1v);
            // layer output for next layer's pre-GEMM / FC
            g_h[t][b0][u]     = h0v;
            g_h[t][b0 + 1][u] = h1v;
        }
        __syncthreads();
    }
}

// ---------------- final FC --------------------------------------------------
#define FCB 128
__global__ void fc_kernel(const float* __restrict__ fc_w,
                          const float* __restrict__ fc_b,
                          float* __restrict__ outp) {
    __shared__ float sh[FCB * Hs];
    __shared__ float sw[NOUT * Hs + NOUT];
    int t   = blockIdx.x;
    int bc  = blockIdx.y;
    int tid = threadIdx.x;

    const float* hbuf = &g_h[0][0][0];
    for (int i = tid; i < FCB * Hs; i += FCB)
        sh[i] = hbuf[(long long)t * BATCH * Hs + (long long)bc * FCB * Hs + i];
    for (int i = tid; i < NOUT * Hs; i += FCB) sw[i] = fc_w[i];
    if (tid < NOUT) sw[NOUT * Hs + tid] = fc_b[tid];
    __syncthreads();

    int b = bc * FCB + tid;
    float o[NOUT];
#pragma unroll
    for (int j = 0; j < NOUT; j++) o[j] = sw[NOUT * Hs + j];
#pragma unroll
    for (int k = 0; k < Hs; k++) {
        float h = sh[tid * Hs + k];
#pragma unroll
        for (int j = 0; j < NOUT; j++) o[j] += h * sw[j * Hs + k];
    }
#pragma unroll
    for (int j = 0; j < NOUT; j++)
        outp[(long long)b * TT * NOUT + t * NOUT + j] = o[j];
}

// ---------------- launcher --------------------------------------------------
extern "C" void kernel_launch(void* const* d_in, const int* in_sizes, int n_in,
                              void* d_out, int out_size) {
    const float* x     = (const float*)d_in[0];
    const float* W_ih0 = (const float*)d_in[1];
    const float* W_ihr = (const float*)d_in[2];
    const float* W_hh  = (const float*)d_in[3];
    const float* b_ih  = (const float*)d_in[4];
    const float* b_hh  = (const float*)d_in[5];
    const float* fc_w  = (const float*)d_in[6];
    const float* fc_b  = (const float*)d_in[7];
    float* outp = (float*)d_out;

    const int pg_smem49 = (49 * HP * 8 + HP * 8 + 49 * IT_PAD) * 4;
    const int pg_smem7  = (7  * HP * 8 + HP * 8 + 7  * IT_PAD) * 4;
    cudaFuncSetAttribute(pre_gemm<49>, cudaFuncAttributeMaxDynamicSharedMemorySize, pg_smem49);
    cudaFuncSetAttribute(pre_gemm<7>,  cudaFuncAttributeMaxDynamicSharedMemorySize, pg_smem7);
    cudaFuncSetAttribute(lstm_rec,     cudaFuncAttributeMaxDynamicSharedMemorySize, R_SMEM);

    const int total = NL * Hs * HP * 4;
    pack_kernel<<<(total + 255) / 256, 256>>>(W_ih0, W_ihr, W_hh, b_ih, b_hh);

    dim3 pgrid(BATCH / PG_BT, TT / PG_TS);
    for (int l = 0; l < NL; l++) {
        if (l == 0) pre_gemm<7><<<pgrid, PG_TPB, pg_smem7>>>(x, l);
        else        pre_gemm<49><<<pgrid, PG_TPB, pg_smem49>>>(x, l);
        lstm_rec<<<BATCH / 8, R_TPB, R_SMEM>>>(l);
    }

    dim3 fcg(TT, BATCH / FCB);
    fc_kernel<<<fcg, FCB>>>(fc_w, fc_b, outp);
}

// round 6
// speedup vs baseline: 2.0337x; 1.3295x over previous
#include <cuda_runtime.h>

typedef unsigned long long ull;

#define Hs      49
#define HP      64
#define G4      196
#define NL      7
#define IN0     7
#define NOUT    7
#define BATCH   1024
#define TT      512

// ---------------- device scratch ------------------------------------------
__device__ float g_wrec[NL][Hs][HP][4];   // recurrent W: [l][k][u][gate i,f,g,o]
__device__ float g_wx[NL][Hs][HP][4];     // input W (non-dup): [l][k][u][gate]
__device__ float g_bias[NL][HP][4];       // b_ih+b_hh (non-dup)
__device__ float g_pre[TT][Hs][BATCH][4]; // input projections [t][u][b][gate]
__device__ float g_h[TT][BATCH][Hs];      // layer output [t][b][u]

// ---------------- f32x2 + fast-activation helpers --------------------------
static __device__ __forceinline__ ull pack2(float lo, float hi) {
    ull r; asm("mov.b64 %0, {%1,%2};" : "=l"(r) : "f"(lo), "f"(hi)); return r;
}
static __device__ __forceinline__ void unpack2(ull v, float &lo, float &hi) {
    asm("mov.b64 {%0,%1}, %2;" : "=f"(lo), "=f"(hi) : "l"(v));
}
static __device__ __forceinline__ ull ffma2(ull a, ull b, ull c) {
    ull d; asm("fma.rn.f32x2 %0, %1, %2, %3;" : "=l"(d) : "l"(a), "l"(b), "l"(c)); return d;
}
static __device__ __forceinline__ ull addf2(ull a, ull b) {
    ull d; asm("add.rn.f32x2 %0, %1, %2;" : "=l"(d) : "l"(a), "l"(b)); return d;
}
static __device__ __forceinline__ float ex2f(float x) {
    float r; asm("ex2.approx.f32 %0, %1;" : "=f"(r) : "f"(x)); return r;
}
static __device__ __forceinline__ float rcpf(float x) {
    float r; asm("rcp.approx.f32 %0, %1;" : "=f"(r) : "f"(x)); return r;
}
#define LOG2E 1.4426950408889634f
static __device__ __forceinline__ float sigf(float x) {
    return rcpf(1.f + ex2f(-LOG2E * x));
}
static __device__ __forceinline__ float tanhf2(float x) {
    return 1.f - 2.f * rcpf(1.f + ex2f(2.f * LOG2E * x));
}

// ---------------- weight / bias packing -----------------------------------
__global__ void pack_kernel(const float* __restrict__ W_ih0,
                            const float* __restrict__ W_ihr,
                            const float* __restrict__ W_hh,
                            const float* __restrict__ b_ih,
                            const float* __restrict__ b_hh) {
    int idx = blockIdx.x * blockDim.x + threadIdx.x;
    const int total = NL * Hs * HP * 4;
    if (idx >= total) return;
    int l   = idx / (Hs * HP * 4);
    int rem = idx % (Hs * HP * 4);
    int k   = rem / (HP * 4);
    int ug  = rem % (HP * 4);
    int u = ug >> 2, j = ug & 3;
    int row = j * Hs + u;                        // torch gate order i,f,g,o

    float wr = 0.f, wx = 0.f;
    if (u < Hs) {
        wr = W_hh[(l * G4 + row) * Hs + k];
        if (l == 0) {
            if (k < IN0) wx = W_ih0[row * IN0 + k];
        } else {
            wx = W_ihr[((l - 1) * G4 + row) * Hs + k];
        }
    }
    g_wrec[l][k][u][j] = wr;
    g_wx[l][k][u][j]   = wx;
    if (k == 0)
        g_bias[l][u][j] = (u < Hs) ? (b_ih[l * G4 + row] + b_hh[l * G4 + row]) : 0.f;
}

// ---------------- input-projection GEMM v2 ----------------------------------
// pre[t][u][b][j] = bias[u][j] + sum_k in[t][b][k] * Wx[k][u][j]
// 256 thr = 8 warps; warp = 8 units x 4 batch-quads; thread = (u, 16 batch rows).
// Inner k: 1 LDS.128 W + 4 dup-movs + 4 LDS.128 X + 32 FFMA2.
#define PG_TPB  256
#define PG_BT   64
#define PG_TS   8
#define ITP     72   // floats per staged k-row (288B, 16B aligned)

template<int KD>
__global__ __launch_bounds__(PG_TPB, 2)
void pre_gemm2(const float* __restrict__ xin, int layer) {
    extern __shared__ float sm[];
    float* ws = sm;                    // [KD][HP][4]
    float* bi = ws + KD * HP * 4;      // [HP][4]
    float* it = bi + HP * 4;           // [KD][ITP]

    const int tid = threadIdx.x;
    const float* wsrc = &g_wx[layer][0][0][0];
    for (int i = tid; i < KD * HP * 4; i += PG_TPB) ws[i] = wsrc[i];
    const float* bsrc = &g_bias[layer][0][0];
    for (int i = tid; i < HP * 4; i += PG_TPB) bi[i] = bsrc[i];

    const int warp = tid >> 5, lane = tid & 31;
    const int u  = (warp << 3) | (lane >> 2);
    const int bq = lane & 3;
    const int bbase = blockIdx.x * PG_BT;
    const int t0    = blockIdx.y * PG_TS;

    // staging: NE elems, thread handles i = tid + r*PG_TPB ; bb = i/KD, k = i%KD
    const int NE   = KD * PG_BT;
    const int NREG = (NE + PG_TPB - 1) / PG_TPB;
    float xr[NREG];
    int   sidx[NREG];     // smem dest index
    long long goff[NREG]; // gmem src offset (t-invariant part)
#pragma unroll
    for (int r = 0; r < NREG; r++) {
        int i = tid + r * PG_TPB;
        if (i < NE) {
            int bb = i / KD, k = i % KD;
            sidx[r] = k * ITP + bb;
            goff[r] = (layer == 0)
                ? ((long long)(bbase + bb) * TT * IN0 + k)       // + t*IN0
                : ((long long)(bbase + bb) * Hs + k);            // + t*BATCH*Hs
        } else { sidx[r] = -1; goff[r] = 0; }
    }
    const long long tstr = (layer == 0) ? (long long)IN0 : (long long)BATCH * Hs;
    const float* src = (layer == 0) ? xin : &g_h[0][0][0];

    // stage tile for t0
#pragma unroll
    for (int r = 0; r < NREG; r++)
        if (sidx[r] >= 0) xr[r] = src[goff[r] + (long long)t0 * tstr];
    __syncthreads();   // W/bias staged
#pragma unroll
    for (int r = 0; r < NREG; r++)
        if (sidx[r] >= 0) it[sidx[r]] = xr[r];
    __syncthreads();

    ull bia[4];
    {
        float4 bv = *(float4*)(bi + u * 4);
        bia[0] = pack2(bv.x, bv.x); bia[1] = pack2(bv.y, bv.y);
        bia[2] = pack2(bv.z, bv.z); bia[3] = pack2(bv.w, bv.w);
    }

    for (int ti = 0; ti < PG_TS; ti++) {
        const int t = t0 + ti;
        // prefetch next tile into regs while computing
        if (ti + 1 < PG_TS) {
#pragma unroll
            for (int r = 0; r < NREG; r++)
                if (sidx[r] >= 0) xr[r] = src[goff[r] + (long long)(t + 1) * tstr];
        }

        ulonglong2 acc[4][4];
#pragma unroll
        for (int g = 0; g < 4; g++)
#pragma unroll
            for (int j = 0; j < 4; j++) { acc[g][j].x = bia[g]; acc[g][j].y = bia[g]; }

#pragma unroll 7
        for (int k = 0; k < KD; k++) {
            float4 w = *(float4*)(ws + (k * HP + u) * 4);
            ull w0 = pack2(w.x, w.x), w1 = pack2(w.y, w.y);
            ull w2 = pack2(w.z, w.z), w3 = pack2(w.w, w.w);
#pragma unroll
            for (int j = 0; j < 4; j++) {
                ulonglong2 X = *(ulonglong2*)(it + k * ITP + bq * 16 + j * 4);
                acc[0][j].x = ffma2(w0, X.x, acc[0][j].x);
                acc[0][j].y = ffma2(w0, X.y, acc[0][j].y);
                acc[1][j].x = ffma2(w1, X.x, acc[1][j].x);
                acc[1][j].y = ffma2(w1, X.y, acc[1][j].y);
                acc[2][j].x = ffma2(w2, X.x, acc[2][j].x);
                acc[2][j].y = ffma2(w2, X.y, acc[2][j].y);
                acc[3][j].x = ffma2(w3, X.x, acc[3][j].x);
                acc[3][j].y = ffma2(w3, X.y, acc[3][j].y);
            }
        }

        if (u < Hs) {
#pragma unroll
            for (int j = 0; j < 4; j++) {
                float iv[4], fv[4], gv[4], ov[4];
                unpack2(acc[0][j].x, iv[0], iv[1]); unpack2(acc[0][j].y, iv[2], iv[3]);
                unpack2(acc[1][j].x, fv[0], fv[1]); unpack2(acc[1][j].y, fv[2], fv[3]);
                unpack2(acc[2][j].x, gv[0], gv[1]); unpack2(acc[2][j].y, gv[2], gv[3]);
                unpack2(acc[3][j].x, ov[0], ov[1]); unpack2(acc[3][j].y, ov[2], ov[3]);
#pragma unroll
                for (int e = 0; e < 4; e++) {
                    int b = bbase + bq * 16 + j * 4 + e;
                    *(float4*)&g_pre[t][u][b][0] = make_float4(iv[e], fv[e], gv[e], ov[e]);
                }
            }
        }
        __syncthreads();            // everyone done reading it
        if (ti + 1 < PG_TS) {
#pragma unroll
            for (int r = 0; r < NREG; r++)
                if (sidx[r] >= 0) it[sidx[r]] = xr[r];
        }
        __syncthreads();
    }
}

// ---------------- recurrent kernel v2 ---------------------------------------
// 128 blocks x 448 threads (14 warps). Warps 0-6 (A): k in [0,25); 7-13 (B): [25,49).
// Thread = (u, batch pair). B writes partial accs to smem; A combines + cell update.
#define R_TPB   448
#define R_SMEM  ((Hs*HP*4 + 2*Hs*16 + 224*8) * 4)

__global__ __launch_bounds__(R_TPB, 1)
void lstm_rec2(int layer) {
    extern __shared__ float sm[];
    float* ws  = sm;                     // [49][HP][4]
    float* vv  = ws + Hs * HP * 4;       // [2][49][8][2] h duplicated pairs
    float* red = vv + 2 * Hs * 16;       // [224][8] B-group partials

    const int tid = threadIdx.x;
    const float* wsrc = &g_wrec[layer][0][0][0];
    for (int i = tid; i < Hs * HP * 4; i += R_TPB) ws[i] = wsrc[i];
    for (int i = tid; i < 2 * Hs * 16; i += R_TPB) vv[i] = 0.f;

    const int w    = tid >> 5, lane = tid & 31;
    const int grp  = (w >= 7);
    const int wu   = grp ? (w - 7) : w;
    const int u    = (wu << 3) | (lane >> 2);
    const int bp   = lane & 3;
    const int b0   = blockIdx.x * 8 + bp * 2;
    const bool act = (u < Hs);
    const int widx = wu * 32 + lane;     // 0..223

    __syncthreads();

    const ulonglong2* wp = (const ulonglong2*)ws;       // idx k*64 + u
    const long long pstride2 = (long long)Hs * BATCH;   // g_pre per-t stride in 16B units

    ull pf0 = 0, pf1 = 0, pf2 = 0, pf3 = 0;
    const ulonglong2* pp0 = (const ulonglong2*)&g_pre[0][act ? u : 0][b0][0];
    if (grp == 0 && act) {
        ulonglong2 A = pp0[0], B = pp0[1];
        pf0 = A.x; pf1 = A.y; pf2 = B.x; pf3 = B.y;
    }

    float c0 = 0.f, c1 = 0.f;

    for (int t = 0; t < TT; t++) {
        const int cur = t & 1, nxt = cur ^ 1;

        ull acc0, acc1, acc2, acc3;
        if (grp == 0) {
            acc0 = pf0; acc1 = pf1; acc2 = pf2; acc3 = pf3;
            if (act && t + 1 < TT) {   // prefetch pre(t+1)
                const ulonglong2* pp = pp0 + (long long)(t + 1) * pstride2;
                ulonglong2 A = pp[0], B = pp[1];
                pf0 = A.x; pf1 = A.y; pf2 = B.x; pf3 = B.y;
            }
        } else {
            acc0 = acc1 = acc2 = acc3 = 0;
        }

        if (act) {
            const ulonglong2* hp = (const ulonglong2*)(vv + cur * Hs * 16);
            if (grp == 0) {
#pragma unroll 5
                for (int k = 0; k < 25; k++) {
                    ulonglong2 W = wp[k * 64 + u];     // (wi,wf),(wg,wo)
                    ulonglong2 H = hp[k * 4 + bp];     // (h0,h0),(h1,h1)
                    acc0 = ffma2(W.x, H.x, acc0);
                    acc1 = ffma2(W.y, H.x, acc1);
                    acc2 = ffma2(W.x, H.y, acc2);
                    acc3 = ffma2(W.y, H.y, acc3);
                }
            } else {
#pragma unroll 6
                for (int k = 25; k < 49; k++) {
                    ulonglong2 W = wp[k * 64 + u];
                    ulonglong2 H = hp[k * 4 + bp];
                    acc0 = ffma2(W.x, H.x, acc0);
                    acc1 = ffma2(W.y, H.x, acc1);
                    acc2 = ffma2(W.x, H.y, acc2);
                    acc3 = ffma2(W.y, H.y, acc3);
                }
                ulonglong2* r = (ulonglong2*)(red + widx * 8);
                r[0] = make_ulonglong2(acc0, acc1);
                r[1] = make_ulonglong2(acc2, acc3);
            }
        }
        __syncthreads();   // B partials visible

        if (grp == 0 && act) {
            const ulonglong2* r = (const ulonglong2*)(red + widx * 8);
            ulonglong2 R0 = r[0], R1 = r[1];
            acc0 = addf2(acc0, R0.x);
            acc1 = addf2(acc1, R0.y);
            acc2 = addf2(acc2, R1.x);
            acc3 = addf2(acc3, R1.y);

            float i0, f0, g0, o0, i1, f1, g1, o1;
            unpack2(acc0, i0, f0);
            unpack2(acc1, g0, o0);
            unpack2(acc2, i1, f1);
            unpack2(acc3, g1, o1);
            i0 = sigf(i0); f0 = sigf(f0); g0 = tanhf2(g0); o0 = sigf(o0);
            i1 = sigf(i1); f1 = sigf(f1); g1 = tanhf2(g1); o1 = sigf(o1);
            c0 = f0 * c0 + i0 * g0;
            c1 = f1 * c1 + i1 * g1;
            float h0v = o0 * tanhf2(c0);
            float h1v = o1 * tanhf2(c1);

            *((float4*)(vv + (nxt * Hs + u) * 16) + bp) = make_float4(h0v, h0v, h1v, h1v);
            g_h[t][b0][u]     = h0v;
            g_h[t][b0 + 1][u] = h1v;
        }
        __syncthreads();   // h(nxt) visible to all
    }
}

// ---------------- final FC --------------------------------------------------
#define FCB 128
__global__ void fc_kernel(const float* __restrict__ fc_w,
                          const float* __restrict__ fc_b,
                          float* __restrict__ outp) {
    __shared__ float sh[FCB * Hs];
    __shared__ float sw[NOUT * Hs + NOUT];
    int t   = blockIdx.x;
    int bc  = blockIdx.y;
    int tid = threadIdx.x;

    const float* hbuf = &g_h[0][0][0];
    for (int i = tid; i < FCB * Hs; i += FCB)
        sh[i] = hbuf[(long long)t * BATCH * Hs + (long long)bc * FCB * Hs + i];
    for (int i = tid; i < NOUT * Hs; i += FCB) sw[i] = fc_w[i];
    if (tid < NOUT) sw[NOUT * Hs + tid] = fc_b[tid];
    __syncthreads();

    int b = bc * FCB + tid;
    float o[NOUT];
#pragma unroll
    for (int j = 0; j < NOUT; j++) o[j] = sw[NOUT * Hs + j];
#pragma unroll
    for (int k = 0; k < Hs; k++) {
        float h = sh[tid * Hs + k];
#pragma unroll
        for (int j = 0; j < NOUT; j++) o[j] += h * sw[j * Hs + k];
    }
#pragma unroll
    for (int j = 0; j < NOUT; j++)
        outp[(long long)b * TT * NOUT + t * NOUT + j] = o[j];
}

// ---------------- launcher --------------------------------------------------
extern "C" void kernel_launch(void* const* d_in, const int* in_sizes, int n_in,
                              void* d_out, int out_size) {
    const float* x     = (const float*)d_in[0];
    const float* W_ih0 = (const float*)d_in[1];
    const float* W_ihr = (const float*)d_in[2];
    const float* W_hh  = (const float*)d_in[3];
    const float* b_ih  = (const float*)d_in[4];
    const float* b_hh  = (const float*)d_in[5];
    const float* fc_w  = (const float*)d_in[6];
    const float* fc_b  = (const float*)d_in[7];
    float* outp = (float*)d_out;

    const int pg_smem49 = (49 * HP * 4 + HP * 4 + 49 * ITP) * 4;
    const int pg_smem7  = (7  * HP * 4 + HP * 4 + 7  * ITP) * 4;
    cudaFuncSetAttribute(pre_gemm2<49>, cudaFuncAttributeMaxDynamicSharedMemorySize, pg_smem49);
    cudaFuncSetAttribute(pre_gemm2<7>,  cudaFuncAttributeMaxDynamicSharedMemorySize, pg_smem7);
    cudaFuncSetAttribute(lstm_rec2,     cudaFuncAttributeMaxDynamicSharedMemorySize, R_SMEM);

    const int total = NL * Hs * HP * 4;
    pack_kernel<<<(total + 255) / 256, 256>>>(W_ih0, W_ihr, W_hh, b_ih, b_hh);

    dim3 pgrid(BATCH / PG_BT, TT / PG_TS);
    for (int l = 0; l < NL; l++) {
        if (l == 0) pre_gemm2<7><<<pgrid, PG_TPB, pg_smem7>>>(x, l);
        else        pre_gemm2<49><<<pgrid, PG_TPB, pg_smem49>>>(x, l);
        lstm_rec2<<<BATCH / 8, R_TPB, R_SMEM>>>(l);
    }

    dim3 fcg(TT, BATCH / FCB);
    fc_kernel<<<fcg, FCB>>>(fc_w, fc_b, outp);
}